// round 1
// baseline (speedup 1.0000x reference)
#include <cuda_runtime.h>

// Model_10582799417658: 127-step LSTM-VAE rollout.
// B=4096, D=64, H=256, GATES=1024, L=64, T=128 (127 scan steps).
//
// Strategy (round 1 baseline):
//  - persistent batch-tiled kernel: 128 CTAs x 256 threads, 32 batch rows/CTA,
//    each CTA runs all 127 steps for its rows (batch rows are independent).
//  - x/h/c/z in SMEM, [k][m] layout (4 batch rows contiguous -> LDS.128).
//  - gate GEMM uses packed fp32x2 FMA (fma.rn.f32x2) -> 2x fp32 throughput.
//  - velo/switch heads folded into rank-1 vectors w_gv/w_ov (prep kernel).

#define B_TOT   4096
#define T_STEPS 127
#define D_IN    64
#define HID     256
#define GATE    1024
#define LAT     64
#define BT      32          // batch rows per CTA
#define NTH     256
#define NCTA    (B_TOT / BT)  // 128
#define MS      36          // padded m-stride in SMEM (floats)

// ---- output layout (tuple flattened in order) ----
#define N_STATES ((unsigned long long)B_TOT * T_STEPS * D_IN)
#define N_GENS   ((unsigned long long)B_TOT * T_STEPS)
#define N_TOTS   ((unsigned long long)B_TOT * 128)
#define O_STATES 0ULL
#define O_GENS   (O_STATES + N_STATES)
#define O_ONOFF  (O_GENS + N_GENS)
#define O_TPRE   (O_ONOFF + N_GENS)
#define O_TPOST  (O_TPRE + N_TOTS)

__device__ float g_wgv[HID];
__device__ float g_wov[HID];
__device__ float g_b2[2];

__device__ __forceinline__ unsigned long long pack2(float a, float b) {
    unsigned long long r;
    asm("mov.b64 %0, {%1,%2};" : "=l"(r)
        : "r"(__float_as_uint(a)), "r"(__float_as_uint(b)));
    return r;
}
__device__ __forceinline__ void fma2(unsigned long long &d,
                                     unsigned long long a,
                                     unsigned long long b) {
    asm("fma.rn.f32x2 %0, %1, %2, %0;" : "+l"(d) : "l"(a), "l"(b));
}
__device__ __forceinline__ float2 unpack2(unsigned long long v) {
    unsigned int lo, hi;
    asm("mov.b64 {%0,%1}, %2;" : "=r"(lo), "=r"(hi) : "l"(v));
    float2 f; f.x = __uint_as_float(lo); f.y = __uint_as_float(hi);
    return f;
}

__device__ __forceinline__ float sig_f(float x) {
    return 1.0f / (1.0f + __expf(-x));
}
__device__ __forceinline__ float tanh_f(float x) {
    // 1 - 2/(e^{2x}+1): exact limits at +/-inf, ~1e-6 rel err mid-range.
    return 1.0f - 2.0f / (__expf(2.0f * x) + 1.0f);
}

// Fold velo/switch heads: w_gv = W_gen @ W_velo, b_gv = W_gen.b_velo + b_gen.
__global__ void prep_kernel(const float* __restrict__ Wgen, const float* __restrict__ bgen,
                            const float* __restrict__ Won,  const float* __restrict__ bon,
                            const float* __restrict__ Wvelo, const float* __restrict__ bvelo,
                            const float* __restrict__ Wsw,  const float* __restrict__ bsw) {
    int k = threadIdx.x;  // 0..255
    float s1 = 0.f, s2 = 0.f;
    #pragma unroll 4
    for (int l = 0; l < LAT; ++l) {
        s1 += Wgen[l] * Wvelo[l * HID + k];
        s2 += Won[l]  * Wsw[l * HID + k];
    }
    g_wgv[k] = s1;
    g_wov[k] = s2;
    if (k == 0) {
        float b1 = bgen[0], b2 = bon[0];
        for (int l = 0; l < LAT; ++l) {
            b1 += Wgen[l] * bvelo[l];
            b2 += Won[l]  * bsw[l];
        }
        g_b2[0] = b1; g_b2[1] = b2;
    }
}

__global__ void __launch_bounds__(NTH, 1)
model_kernel(const float* __restrict__ data, const float* __restrict__ locs,
             const float* __restrict__ Wih,  const float* __restrict__ Whh,
             const float* __restrict__ bih,  const float* __restrict__ bhh,
             const float* __restrict__ Wmu,  const float* __restrict__ bmu,
             const float* __restrict__ Wvar, const float* __restrict__ bvar,
             const float* __restrict__ Wnext, const float* __restrict__ bnext,
             const float* __restrict__ Wloc, const float* __restrict__ bloc,
             const float* __restrict__ eps,  float* __restrict__ out) {
    extern __shared__ float sm[];
    float* xs   = sm;                   // [64][MS]  current state x (transposed)
    float* hsA  = xs  + D_IN * MS;      // [256][MS]
    float* hsB  = hsA + HID * MS;       // [256][MS]
    float* cs   = hsB + HID * MS;       // [256][MS]
    float* zs   = cs  + HID * MS;       // [64][MS]
    float* bsum = zs  + D_IN * MS;      // [1024]  b_ih + b_hh
    float* wgv  = bsum + GATE;          // [256]
    float* wov  = wgv + HID;            // [256]
    float* abuf = wov + HID;            // [32]  generate*on per row

    const int tid   = threadIdx.x;
    const int bBase = blockIdx.x * BT;

    // ---------------- init ----------------
    for (int i = tid; i < HID * MS; i += NTH) cs[i] = 0.f;
    for (int i = tid; i < D_IN * BT; i += NTH) {
        int k = i / BT, m = i % BT;
        xs[k * MS + m] = data[(size_t)(bBase + m) * (128 * D_IN) + k];  // data[b][0][k]
    }
    for (int i = tid; i < HID * BT; i += NTH) {
        int j = i / BT, m = i % BT;
        int b = bBase + m;
        hsA[j * MS + m] = locs[b * 2] * Wloc[j * 2] + locs[b * 2 + 1] * Wloc[j * 2 + 1] + bloc[j];
    }
    for (int i = tid; i < GATE; i += NTH) bsum[i] = bih[i] + bhh[i];
    for (int i = tid; i < HID; i += NTH) { wgv[i] = g_wgv[i]; wov[i] = g_wov[i]; }
    if (tid < BT) {
        out[O_TPRE  + (size_t)(bBase + tid) * 128] = 0.f;   // totals at tt=0
        out[O_TPOST + (size_t)(bBase + tid) * 128] = 0.f;
    }
    const float bgv = g_b2[0], bov = g_b2[1];
    __syncthreads();

    float* hC = hsA;  // h_old (read by gate GEMM)
    float* hN = hsB;  // h_new (written this step)

    const int mt = tid & 7;         // 8 m-tiles of 4 rows
    const int jt = tid >> 3;        // 32 j-tiles of 2 hidden cols
    const int m0 = mt * 4;
    const int wrp = tid >> 5, lane = tid & 31;

    for (int t = 0; t < T_STEPS; ++t) {
        // ======== Phase 1: gates = x@Wih^T + h@Whh^T, LSTM update ========
        for (int jc = 0; jc < 4; ++jc) {          // hidden chunks of 64
            const int j0 = jc * 64 + jt * 2;
            unsigned long long A[16];
            #pragma unroll
            for (int i = 0; i < 16; ++i) A[i] = 0ULL;

            const float* wp[8];
            #pragma unroll
            for (int g = 0; g < 4; ++g)
                #pragma unroll
                for (int jj = 0; jj < 2; ++jj)
                    wp[g * 2 + jj] = Wih + (size_t)(g * HID + j0 + jj) * D_IN;

            // part A: K = 64 over x
            #pragma unroll 2
            for (int k0 = 0; k0 < D_IN; k0 += 4) {
                float4 wf[8];
                #pragma unroll
                for (int i2 = 0; i2 < 8; ++i2)
                    wf[i2] = *(const float4*)(wp[i2] + k0);
                #pragma unroll
                for (int kk = 0; kk < 4; ++kk) {
                    ulonglong2 av = *(const ulonglong2*)(xs + (k0 + kk) * MS + m0);
                    #pragma unroll
                    for (int i2 = 0; i2 < 8; ++i2) {
                        float w = (&wf[i2].x)[kk];
                        unsigned long long w2 = pack2(w, w);
                        fma2(A[i2 * 2 + 0], av.x, w2);
                        fma2(A[i2 * 2 + 1], av.y, w2);
                    }
                }
            }
            // part B: K = 256 over h_old
            #pragma unroll
            for (int g = 0; g < 4; ++g)
                #pragma unroll
                for (int jj = 0; jj < 2; ++jj)
                    wp[g * 2 + jj] = Whh + (size_t)(g * HID + j0 + jj) * HID;
            #pragma unroll 2
            for (int k0 = 0; k0 < HID; k0 += 4) {
                float4 wf[8];
                #pragma unroll
                for (int i2 = 0; i2 < 8; ++i2)
                    wf[i2] = *(const float4*)(wp[i2] + k0);
                #pragma unroll
                for (int kk = 0; kk < 4; ++kk) {
                    ulonglong2 av = *(const ulonglong2*)(hC + (k0 + kk) * MS + m0);
                    #pragma unroll
                    for (int i2 = 0; i2 < 8; ++i2) {
                        float w = (&wf[i2].x)[kk];
                        unsigned long long w2 = pack2(w, w);
                        fma2(A[i2 * 2 + 0], av.x, w2);
                        fma2(A[i2 * 2 + 1], av.y, w2);
                    }
                }
            }
            // epilogue: bias + nonlinearities + c/h update
            #pragma unroll
            for (int jj = 0; jj < 2; ++jj) {
                const int j = j0 + jj;
                const float bi = bsum[j];
                const float bf = bsum[HID + j];
                const float bg = bsum[2 * HID + j];
                const float bo = bsum[3 * HID + j];
                float2 i01 = unpack2(A[(0 * 2 + jj) * 2 + 0]), i23 = unpack2(A[(0 * 2 + jj) * 2 + 1]);
                float2 f01 = unpack2(A[(1 * 2 + jj) * 2 + 0]), f23 = unpack2(A[(1 * 2 + jj) * 2 + 1]);
                float2 g01 = unpack2(A[(2 * 2 + jj) * 2 + 0]), g23 = unpack2(A[(2 * 2 + jj) * 2 + 1]);
                float2 o01 = unpack2(A[(3 * 2 + jj) * 2 + 0]), o23 = unpack2(A[(3 * 2 + jj) * 2 + 1]);
                float gi[4] = {i01.x, i01.y, i23.x, i23.y};
                float gf[4] = {f01.x, f01.y, f23.x, f23.y};
                float gg[4] = {g01.x, g01.y, g23.x, g23.y};
                float go[4] = {o01.x, o01.y, o23.x, o23.y};
                #pragma unroll
                for (int r = 0; r < 4; ++r) {
                    const int m = m0 + r;
                    float iv = sig_f(gi[r] + bi);
                    float fv = sig_f(gf[r] + bf);
                    float gv = tanh_f(gg[r] + bg);
                    float ov = sig_f(go[r] + bo);
                    float c = fv * cs[j * MS + m] + iv * gv;
                    cs[j * MS + m] = c;
                    hN[j * MS + m] = ov * tanh_f(c);
                }
            }
        }
        __syncthreads();

        // ======== Phase 2: mu/logvar heads, z, gen/on ========
        for (int r = 0; r < 4; ++r) {
            const int m = wrp * 4 + r;
            const int b = bBase + m;
            float amu0 = 0.f, amu1 = 0.f, alv0 = 0.f, alv1 = 0.f;
            const float* wm0 = Wmu  + (size_t)lane * HID;
            const float* wm1 = Wmu  + (size_t)(lane + 32) * HID;
            const float* wv0 = Wvar + (size_t)lane * HID;
            const float* wv1 = Wvar + (size_t)(lane + 32) * HID;
            #pragma unroll 2
            for (int k0 = 0; k0 < HID; k0 += 4) {
                float a0 = hN[(k0 + 0) * MS + m];
                float a1 = hN[(k0 + 1) * MS + m];
                float a2 = hN[(k0 + 2) * MS + m];
                float a3 = hN[(k0 + 3) * MS + m];
                float4 wA = *(const float4*)(wm0 + k0);
                float4 wB = *(const float4*)(wm1 + k0);
                float4 wC = *(const float4*)(wv0 + k0);
                float4 wD = *(const float4*)(wv1 + k0);
                amu0 = fmaf(a0, wA.x, fmaf(a1, wA.y, fmaf(a2, wA.z, fmaf(a3, wA.w, amu0))));
                amu1 = fmaf(a0, wB.x, fmaf(a1, wB.y, fmaf(a2, wB.z, fmaf(a3, wB.w, amu1))));
                alv0 = fmaf(a0, wC.x, fmaf(a1, wC.y, fmaf(a2, wC.z, fmaf(a3, wC.w, alv0))));
                alv1 = fmaf(a0, wD.x, fmaf(a1, wD.y, fmaf(a2, wD.z, fmaf(a3, wD.w, alv1))));
            }
            float mu0 = amu0 + bmu[lane];
            float mu1 = amu1 + bmu[lane + 32];
            float lv0 = alv0 + bvar[lane];
            float lv1 = alv1 + bvar[lane + 32];

            float gp = 0.f, op = 0.f;
            #pragma unroll
            for (int i2 = 0; i2 < 8; ++i2) {
                int k = lane + 32 * i2;
                float hv = hN[k * MS + m];
                gp = fmaf(hv, wgv[k], gp);
                op = fmaf(hv, wov[k], op);
            }
            #pragma unroll
            for (int s2 = 16; s2 > 0; s2 >>= 1) {
                gp += __shfl_xor_sync(0xffffffffu, gp, s2);
                op += __shfl_xor_sync(0xffffffffu, op, s2);
            }
            if (lane == 0) {
                float gen = fmaxf(gp + bgv, 0.f);
                float on  = (op + bov) > 0.f ? 1.f : 0.f;
                abuf[m] = gen * on;
                out[O_GENS  + (size_t)b * T_STEPS + t] = gen;
                out[O_ONOFF + (size_t)b * T_STEPS + t] = on;
            }
            const float* ep = eps + ((size_t)t * B_TOT + b) * LAT;
            zs[lane * MS + m]        = ep[lane]      * __expf(0.5f * lv0) + mu0;
            zs[(lane + 32) * MS + m] = ep[lane + 32] * __expf(0.5f * lv1) + mu1;
        }
        __syncwarp();  // zs/abuf produced and consumed within the same warp

        // ======== Phase 3: delta = z@Wnext^T, state update, totals ========
        for (int r = 0; r < 4; ++r) {
            const int m = wrp * 4 + r;
            const int b = bBase + m;
            float d0 = bnext[lane], d1 = bnext[lane + 32];
            const float* wn0 = Wnext + (size_t)lane * LAT;
            const float* wn1 = Wnext + (size_t)(lane + 32) * LAT;
            #pragma unroll 2
            for (int k0 = 0; k0 < LAT; k0 += 4) {
                #pragma unroll
                for (int kk = 0; kk < 4; ++kk) {
                    float zk = zs[(k0 + kk) * MS + m];
                    d0 = fmaf(zk, wn0[k0 + kk], d0);
                    d1 = fmaf(zk, wn1[k0 + kk], d1);
                }
            }
            float xn0 = (lane == 0) ? 0.f : fmaxf(xs[lane * MS + m] + d0, 0.f);
            float xn1 = fmaxf(xs[(lane + 32) * MS + m] + d1, 0.f);
            float part = xn0 + xn1;
            #pragma unroll
            for (int s2 = 16; s2 > 0; s2 >>= 1)
                part += __shfl_xor_sync(0xffffffffu, part, s2);
            float add = abuf[m];
            float v0 = (lane == 0) ? add : xn0;
            size_t ob = O_STATES + ((size_t)b * T_STEPS + t) * D_IN;
            out[ob + lane]      = v0;
            out[ob + lane + 32] = xn1;
            xs[lane * MS + m]        = v0;
            xs[(lane + 32) * MS + m] = xn1;
            if (lane == 0) {
                out[O_TPRE  + (size_t)b * 128 + t + 1] = part;
                out[O_TPOST + (size_t)b * 128 + t + 1] = part + add;
            }
        }
        // swap h buffers; sync makes xs/hN visible to all threads for next step
        float* tmpp = hC; hC = hN; hN = tmpp;
        __syncthreads();
    }
}

extern "C" void kernel_launch(void* const* d_in, const int* in_sizes, int n_in,
                              void* d_out, int out_size) {
    const float* data  = (const float*)d_in[0];
    const float* locs  = (const float*)d_in[1];
    const float* Wih   = (const float*)d_in[2];
    const float* Whh   = (const float*)d_in[3];
    const float* bih   = (const float*)d_in[4];
    const float* bhh   = (const float*)d_in[5];
    const float* Wmu   = (const float*)d_in[6];
    const float* bmu   = (const float*)d_in[7];
    const float* Wvar  = (const float*)d_in[8];
    const float* bvar  = (const float*)d_in[9];
    const float* Wvelo = (const float*)d_in[10];
    const float* bvelo = (const float*)d_in[11];
    const float* Wsw   = (const float*)d_in[12];
    const float* bsw   = (const float*)d_in[13];
    const float* Wgen  = (const float*)d_in[14];
    const float* bgen  = (const float*)d_in[15];
    const float* Won   = (const float*)d_in[16];
    const float* bon   = (const float*)d_in[17];
    const float* Wnext = (const float*)d_in[18];
    const float* bnext = (const float*)d_in[19];
    const float* Wloc  = (const float*)d_in[20];
    const float* bloc  = (const float*)d_in[21];
    const float* eps   = (const float*)d_in[22];
    float* out = (float*)d_out;

    prep_kernel<<<1, 256>>>(Wgen, bgen, Won, bon, Wvelo, bvelo, Wsw, bsw);

    // floats: xs 2304 + hsA 9216 + hsB 9216 + cs 9216 + zs 2304
    //         + bsum 1024 + wgv 256 + wov 256 + abuf 32 = 33824
    const size_t smem_bytes = 33824 * sizeof(float);  // 135,296 B
    cudaFuncSetAttribute(model_kernel,
                         cudaFuncAttributeMaxDynamicSharedMemorySize,
                         (int)smem_bytes);
    model_kernel<<<NCTA, NTH, smem_bytes>>>(data, locs, Wih, Whh, bih, bhh,
                                            Wmu, bmu, Wvar, bvar, Wnext, bnext,
                                            Wloc, bloc, eps, out);
}

// round 2
// speedup vs baseline: 1.9389x; 1.9389x over previous
#include <cuda_runtime.h>

// Model_10582799417658: 127-step LSTM-VAE rollout.
// B=4096, D=64, H=256, GATES=1024, L=64, T=128 (127 scan steps).
//
// Round 2: SMEM-staged double-buffered weight panels (kills the L2-latency
// stalls that held round 1 at issue=12.5%), 512 threads/CTA, j-pair-packed
// FFMA2 accumulators (weights feed fma.rn.f32x2 directly from LDS.64).

#define B_TOT   4096
#define T_STEPS 127
#define D_IN    64
#define HID     256
#define GATE    1024
#define LAT     64
#define BT      32
#define NTH     512
#define NCTA    (B_TOT / BT)   // 128
#define MS      36             // padded m-stride (floats)
#define PK      16             // weight panel depth (k)
#define NP1     20             // phase-1 panels: K=320 / 16
#define NP2     16             // phase-2 panels: K=256 / 16
#define SROW1   512            // phase-1 panel row count
#define SROW2   128            // phase-2 panel row count

// ---- output layout ----
#define N_STATES ((unsigned long long)B_TOT * T_STEPS * D_IN)
#define N_GENS   ((unsigned long long)B_TOT * T_STEPS)
#define N_TOTS   ((unsigned long long)B_TOT * 128)
#define O_STATES 0ULL
#define O_GENS   (O_STATES + N_STATES)
#define O_ONOFF  (O_GENS + N_GENS)
#define O_TPRE   (O_ONOFF + N_GENS)
#define O_TPOST  (O_TPRE + N_TOTS)

typedef unsigned long long ull;

__device__ float g_wgv[HID];
__device__ float g_wov[HID];
__device__ float g_b2[2];

__device__ __forceinline__ ull pack2s(float a) {   // splat (a, a)
    ull r;
    asm("mov.b64 %0, {%1,%1};" : "=l"(r) : "r"(__float_as_uint(a)));
    return r;
}
__device__ __forceinline__ void fma2(ull &d, ull a, ull b) {
    asm("fma.rn.f32x2 %0, %1, %2, %0;" : "+l"(d) : "l"(a), "l"(b));
}
__device__ __forceinline__ float2 unpack2(ull v) {
    unsigned int lo, hi;
    asm("mov.b64 {%0,%1}, %2;" : "=r"(lo), "=r"(hi) : "l"(v));
    float2 f; f.x = __uint_as_float(lo); f.y = __uint_as_float(hi);
    return f;
}
__device__ __forceinline__ float sig_f(float x) {
    return 1.0f / (1.0f + __expf(-x));
}
__device__ __forceinline__ float tanh_f(float x) {
    return 1.0f - 2.0f / (__expf(2.0f * x) + 1.0f);
}

// Fold velo/switch heads into rank-1 vectors.
__global__ void prep_kernel(const float* __restrict__ Wgen, const float* __restrict__ bgen,
                            const float* __restrict__ Won,  const float* __restrict__ bon,
                            const float* __restrict__ Wvelo, const float* __restrict__ bvelo,
                            const float* __restrict__ Wsw,  const float* __restrict__ bsw) {
    int k = threadIdx.x;
    float s1 = 0.f, s2 = 0.f;
    #pragma unroll 4
    for (int l = 0; l < LAT; ++l) {
        s1 += Wgen[l] * Wvelo[l * HID + k];
        s2 += Won[l]  * Wsw[l * HID + k];
    }
    g_wgv[k] = s1;
    g_wov[k] = s2;
    if (k == 0) {
        float b1 = bgen[0], b2 = bon[0];
        for (int l = 0; l < LAT; ++l) {
            b1 += Wgen[l] * bvelo[l];
            b2 += Won[l]  * bsw[l];
        }
        g_b2[0] = b1; g_b2[1] = b2;
    }
}

__global__ void __launch_bounds__(NTH, 1)
model_kernel(const float* __restrict__ data, const float* __restrict__ locs,
             const float* __restrict__ Wih,  const float* __restrict__ Whh,
             const float* __restrict__ bih,  const float* __restrict__ bhh,
             const float* __restrict__ Wmu,  const float* __restrict__ bmu,
             const float* __restrict__ Wvar, const float* __restrict__ bvar,
             const float* __restrict__ Wnext, const float* __restrict__ bnext,
             const float* __restrict__ Wloc, const float* __restrict__ bloc,
             const float* __restrict__ eps,  float* __restrict__ out) {
    extern __shared__ float sm[];
    float* xs     = sm;                  // [64][MS]
    float* hsA    = xs     + 2304;       // [256][MS]
    float* hsB    = hsA    + 9216;
    float* cs     = hsB    + 9216;
    float* zs     = cs     + 9216;       // [64][MS]
    float* bsum   = zs     + 2304;       // [1024]
    float* wgv    = bsum   + 1024;       // [256]
    float* wov    = wgv    + 256;        // [256]
    float* bmu_s  = wov    + 256;        // [64]
    float* bvar_s = bmu_s  + 64;         // [64]
    float* bnx_s  = bvar_s + 64;         // [64]
    float* wnT    = bnx_s  + 64;         // [64][64]  Wnext transposed
    float* abuf   = wnT    + 4096;       // [32]
    float* wbA    = abuf   + 32;         // [PK][512] panel buf A (8192)
    float* wbB    = wbA    + 8192;       // panel buf B (8192)
    float* mus    = wbA;                 // [64][MS] (reuse panel buf between phases)
    float* lvs    = wbA + 2304;          // [64][MS]
    float* wbuf[2] = { wbA, wbB };

    const int tid   = threadIdx.x;
    const int bBase = blockIdx.x * BT;
    const int mt  = tid & 7;
    const int jt  = tid >> 3;            // 0..63
    const int m0  = mt * 4;
    const int jt2 = jt * 2;
    const int wrp = tid >> 5, lane = tid & 31;

    // ---------------- init ----------------
    for (int i = tid; i < HID * MS; i += NTH) cs[i] = 0.f;
    for (int i = tid; i < D_IN * BT; i += NTH) {
        int k = i / BT, m = i % BT;
        xs[k * MS + m] = data[(size_t)(bBase + m) * (128 * D_IN) + k];
    }
    for (int i = tid; i < HID * BT; i += NTH) {
        int j = i / BT, m = i % BT;
        int b = bBase + m;
        hsA[j * MS + m] = locs[b * 2] * Wloc[j * 2] + locs[b * 2 + 1] * Wloc[j * 2 + 1] + bloc[j];
    }
    for (int i = tid; i < GATE; i += NTH) bsum[i] = bih[i] + bhh[i];
    for (int i = tid; i < HID; i += NTH) { wgv[i] = g_wgv[i]; wov[i] = g_wov[i]; }
    for (int i = tid; i < LAT; i += NTH) { bmu_s[i] = bmu[i]; bvar_s[i] = bvar[i]; }
    for (int i = tid; i < D_IN; i += NTH) bnx_s[i] = bnext[i];
    for (int i = tid; i < LAT * D_IN; i += NTH) {   // wnT[l][c] = Wnext[c][l]
        int l = i >> 6, c = i & 63;
        wnT[i] = Wnext[c * LAT + l];
    }
    if (tid < BT) {
        out[O_TPRE  + (size_t)(bBase + tid) * 128] = 0.f;
        out[O_TPOST + (size_t)(bBase + tid) * 128] = 0.f;
    }
    const float bgv = g_b2[0], bov = g_b2[1];
    __syncthreads();

    float* hC = hsA;     // h_old
    float* hN = hsB;     // h_new

    for (int t = 0; t < T_STEPS; ++t) {
        // prefetch eps for phase 2b (DRAM latency hidden under phase 1)
        float ea[2], eb[2];
        {
            const int mr = wrp * 2;
            const float* ep = eps + ((size_t)t * B_TOT + bBase + mr) * LAT;
            ea[0] = __ldg(ep + lane);        eb[0] = __ldg(ep + lane + 32);
            ea[1] = __ldg(ep + LAT + lane);  eb[1] = __ldg(ep + LAT + lane + 32);
        }

        // ======== Phase 1: gates GEMM (j-chunks of 128 hidden cols) ========
        for (int jc = 0; jc < 2; ++jc) {
            const int r = tid;             // panel row owned for loading
            const int gg_ = r >> 7, col_ = r & 127;
            const int grow = gg_ * 256 + jc * 128 + col_;
            const float* rowIh = Wih + (size_t)grow * D_IN;
            const float* rowHh = Whh + (size_t)grow * HID;

            auto ld1 = [&](int p, float4* pf) {
                const int k0 = p * PK;
                const float* ptr = (k0 < 64) ? (rowIh + k0) : (rowHh + (k0 - 64));
                pf[0] = *(const float4*)(ptr + 0);
                pf[1] = *(const float4*)(ptr + 4);
                pf[2] = *(const float4*)(ptr + 8);
                pf[3] = *(const float4*)(ptr + 12);
            };
            auto st1 = [&](int p, const float4* pf) {
                float* wb = wbuf[p & 1];
                #pragma unroll
                for (int q = 0; q < 4; ++q) {
                    wb[(q * 4 + 0) * SROW1 + r] = pf[q].x;
                    wb[(q * 4 + 1) * SROW1 + r] = pf[q].y;
                    wb[(q * 4 + 2) * SROW1 + r] = pf[q].z;
                    wb[(q * 4 + 3) * SROW1 + r] = pf[q].w;
                }
            };

            ull acc[16];
            #pragma unroll
            for (int i = 0; i < 16; ++i) acc[i] = 0ULL;

            float4 pf[4];
            { float4 t0[4]; ld1(0, t0); st1(0, t0); }
            ld1(1, pf);
            __syncthreads();

            for (int p = 0; p < NP1; ++p) {
                if (p + 1 < NP1) st1(p + 1, pf);
                if (p + 2 < NP1) ld1(p + 2, pf);
                const float* wc = wbuf[p & 1];
                const int k0 = p * PK;
                const float* Ab = (p < 4) ? (xs + k0 * MS) : (hC + (k0 - 64) * MS);
                #pragma unroll
                for (int kk = 0; kk < PK; ++kk) {
                    float4 a = *(const float4*)(Ab + kk * MS + m0);
                    ull am0 = pack2s(a.x), am1 = pack2s(a.y);
                    ull am2 = pack2s(a.z), am3 = pack2s(a.w);
                    const float* wr = wc + kk * SROW1 + jt2;
                    #pragma unroll
                    for (int g = 0; g < 4; ++g) {
                        ull w = *(const ull*)(wr + g * 128);
                        fma2(acc[0 * 4 + g], am0, w);
                        fma2(acc[1 * 4 + g], am1, w);
                        fma2(acc[2 * 4 + g], am2, w);
                        fma2(acc[3 * 4 + g], am3, w);
                    }
                }
                __syncthreads();
            }

            // epilogue: bias + LSTM nonlinearity for hidden cols (hj0, hj1)
            const int hj0 = jc * 128 + jt2, hj1 = hj0 + 1;
            const float bi0 = bsum[hj0],       bi1 = bsum[hj1];
            const float bf0 = bsum[256 + hj0], bf1 = bsum[256 + hj1];
            const float bg0 = bsum[512 + hj0], bg1 = bsum[512 + hj1];
            const float bo0 = bsum[768 + hj0], bo1 = bsum[768 + hj1];
            #pragma unroll
            for (int m = 0; m < 4; ++m) {
                const int mm = m0 + m;
                float2 vi = unpack2(acc[m * 4 + 0]);
                float2 vf = unpack2(acc[m * 4 + 1]);
                float2 vg = unpack2(acc[m * 4 + 2]);
                float2 vo = unpack2(acc[m * 4 + 3]);
                {
                    float iv = sig_f(vi.x + bi0), fv = sig_f(vf.x + bf0);
                    float gv = tanh_f(vg.x + bg0), ov = sig_f(vo.x + bo0);
                    float c = fv * cs[hj0 * MS + mm] + iv * gv;
                    cs[hj0 * MS + mm] = c;
                    hN[hj0 * MS + mm] = ov * tanh_f(c);
                }
                {
                    float iv = sig_f(vi.y + bi1), fv = sig_f(vf.y + bf1);
                    float gv = tanh_f(vg.y + bg1), ov = sig_f(vo.y + bo1);
                    float c = fv * cs[hj1 * MS + mm] + iv * gv;
                    cs[hj1 * MS + mm] = c;
                    hN[hj1 * MS + mm] = ov * tanh_f(c);
                }
            }
        }

        // ======== Phase 2a: [mu;logvar] = hN @ [Wmu;Wvar]^T (panel GEMM) ====
        {
            const int r2 = tid & 127, q2 = tid >> 7;
            const float* row2 = (r2 < 64) ? (Wmu + (size_t)r2 * HID)
                                          : (Wvar + (size_t)(r2 - 64) * HID);
            auto ld2 = [&](int p, float4* pf) {
                *pf = *(const float4*)(row2 + p * PK + q2 * 4);
            };
            auto st2 = [&](int p, const float4* pf) {
                float* wb = wbuf[p & 1];
                wb[(q2 * 4 + 0) * SROW2 + r2] = pf->x;
                wb[(q2 * 4 + 1) * SROW2 + r2] = pf->y;
                wb[(q2 * 4 + 2) * SROW2 + r2] = pf->z;
                wb[(q2 * 4 + 3) * SROW2 + r2] = pf->w;
            };

            ull acc2[4] = {0ULL, 0ULL, 0ULL, 0ULL};
            float4 pf2;
            { float4 t0; ld2(0, &t0); st2(0, &t0); }
            ld2(1, &pf2);
            __syncthreads();

            for (int p = 0; p < NP2; ++p) {
                if (p + 1 < NP2) st2(p + 1, &pf2);
                if (p + 2 < NP2) ld2(p + 2, &pf2);
                const float* wc = wbuf[p & 1];
                const int k0 = p * PK;
                #pragma unroll
                for (int kk = 0; kk < PK; ++kk) {
                    float4 a = *(const float4*)(hN + (k0 + kk) * MS + m0);
                    ull w = *(const ull*)(wc + kk * SROW2 + jt2);
                    fma2(acc2[0], pack2s(a.x), w);
                    fma2(acc2[1], pack2s(a.y), w);
                    fma2(acc2[2], pack2s(a.z), w);
                    fma2(acc2[3], pack2s(a.w), w);
                }
                __syncthreads();
            }
            // epilogue: rows (jt2, jt2+1) of the 128-row [mu;logvar] block
            if (jt2 < 64) {
                const float b0 = bmu_s[jt2], b1 = bmu_s[jt2 + 1];
                #pragma unroll
                for (int m = 0; m < 4; ++m) {
                    float2 v = unpack2(acc2[m]);
                    mus[jt2 * MS + m0 + m]       = v.x + b0;
                    mus[(jt2 + 1) * MS + m0 + m] = v.y + b1;
                }
            } else {
                const int l0 = jt2 - 64;
                const float b0 = bvar_s[l0], b1 = bvar_s[l0 + 1];
                #pragma unroll
                for (int m = 0; m < 4; ++m) {
                    float2 v = unpack2(acc2[m]);
                    lvs[l0 * MS + m0 + m]       = v.x + b0;
                    lvs[(l0 + 1) * MS + m0 + m] = v.y + b1;
                }
            }
        }
        __syncthreads();

        // ======== Phase 2b: gen/on + reparameterized z ========
        #pragma unroll
        for (int r = 0; r < 2; ++r) {
            const int m = wrp * 2 + r;
            const int b = bBase + m;
            float gp = 0.f, op = 0.f;
            #pragma unroll
            for (int i2 = 0; i2 < 8; ++i2) {
                int k = lane + 32 * i2;
                float hv = hN[k * MS + m];
                gp = fmaf(hv, wgv[k], gp);
                op = fmaf(hv, wov[k], op);
            }
            #pragma unroll
            for (int s2 = 16; s2 > 0; s2 >>= 1) {
                gp += __shfl_xor_sync(0xffffffffu, gp, s2);
                op += __shfl_xor_sync(0xffffffffu, op, s2);
            }
            if (lane == 0) {
                float gen = fmaxf(gp + bgv, 0.f);
                float on  = (op + bov) > 0.f ? 1.f : 0.f;
                abuf[m] = gen * on;
                out[O_GENS  + (size_t)b * T_STEPS + t] = gen;
                out[O_ONOFF + (size_t)b * T_STEPS + t] = on;
            }
            float mu0 = mus[lane * MS + m],        lv0 = lvs[lane * MS + m];
            float mu1 = mus[(lane + 32) * MS + m], lv1 = lvs[(lane + 32) * MS + m];
            zs[lane * MS + m]        = ea[r] * __expf(0.5f * lv0) + mu0;
            zs[(lane + 32) * MS + m] = eb[r] * __expf(0.5f * lv1) + mu1;
        }
        __syncwarp();

        // ======== Phase 3: delta = z@Wnext^T, state update, totals ========
        #pragma unroll
        for (int r = 0; r < 2; ++r) {
            const int m = wrp * 2 + r;
            const int b = bBase + m;
            float d0 = bnx_s[lane], d1 = bnx_s[lane + 32];
            #pragma unroll 8
            for (int l = 0; l < LAT; ++l) {
                float zl = zs[l * MS + m];
                d0 = fmaf(zl, wnT[l * 64 + lane],      d0);
                d1 = fmaf(zl, wnT[l * 64 + lane + 32], d1);
            }
            float xn0 = (lane == 0) ? 0.f : fmaxf(xs[lane * MS + m] + d0, 0.f);
            float xn1 = fmaxf(xs[(lane + 32) * MS + m] + d1, 0.f);
            float part = xn0 + xn1;
            #pragma unroll
            for (int s2 = 16; s2 > 0; s2 >>= 1)
                part += __shfl_xor_sync(0xffffffffu, part, s2);
            float add = abuf[m];
            float v0 = (lane == 0) ? add : xn0;
            size_t ob = O_STATES + ((size_t)b * T_STEPS + t) * D_IN;
            out[ob + lane]      = v0;
            out[ob + lane + 32] = xn1;
            xs[lane * MS + m]        = v0;
            xs[(lane + 32) * MS + m] = xn1;
            if (lane == 0) {
                out[O_TPRE  + (size_t)b * 128 + t + 1] = part;
                out[O_TPOST + (size_t)b * 128 + t + 1] = part + add;
            }
        }
        float* tmpp = hC; hC = hN; hN = tmpp;
        __syncthreads();
    }
}

extern "C" void kernel_launch(void* const* d_in, const int* in_sizes, int n_in,
                              void* d_out, int out_size) {
    const float* data  = (const float*)d_in[0];
    const float* locs  = (const float*)d_in[1];
    const float* Wih   = (const float*)d_in[2];
    const float* Whh   = (const float*)d_in[3];
    const float* bih   = (const float*)d_in[4];
    const float* bhh   = (const float*)d_in[5];
    const float* Wmu   = (const float*)d_in[6];
    const float* bmu   = (const float*)d_in[7];
    const float* Wvar  = (const float*)d_in[8];
    const float* bvar  = (const float*)d_in[9];
    const float* Wvelo = (const float*)d_in[10];
    const float* bvelo = (const float*)d_in[11];
    const float* Wsw   = (const float*)d_in[12];
    const float* bsw   = (const float*)d_in[13];
    const float* Wgen  = (const float*)d_in[14];
    const float* bgen  = (const float*)d_in[15];
    const float* Won   = (const float*)d_in[16];
    const float* bon   = (const float*)d_in[17];
    const float* Wnext = (const float*)d_in[18];
    const float* bnext = (const float*)d_in[19];
    const float* Wloc  = (const float*)d_in[20];
    const float* bloc  = (const float*)d_in[21];
    const float* eps   = (const float*)d_in[22];
    float* out = (float*)d_out;

    prep_kernel<<<1, 256>>>(Wgen, bgen, Won, bon, Wvelo, bvelo, Wsw, bsw);

    const size_t smem_bytes = 54496 * sizeof(float);  // 217,984 B
    cudaFuncSetAttribute(model_kernel,
                         cudaFuncAttributeMaxDynamicSharedMemorySize,
                         (int)smem_bytes);
    model_kernel<<<NCTA, NTH, smem_bytes>>>(data, locs, Wih, Whh, bih, bhh,
                                            Wmu, bmu, Wvar, bvar, Wnext, bnext,
                                            Wloc, bloc, eps, out);
}